// round 1
// baseline (speedup 1.0000x reference)
#include <cuda_runtime.h>
#include <math.h>

// Problem-instance constants (from setup_inputs: b=2, h=240, w=320, n=2*h*w)
#define BB 2
#define NN 153600
#define HH 240
#define WW 320
#define HWp (HH * WW)
#define PLANE (BB * HWp)        // 153600 pixels total
#define TOTAL (5 * PLANE)       // depth + conf + 3 rgb planes = 768000 floats
#define ZNEAR 0.1f
#define ZFAR 1000.0f

// Scratch (no allocations allowed -> __device__ globals)
__device__ unsigned g_key[PLANE];        // per-pixel packed winner key
__device__ unsigned g_minmax[2 * BB];    // [dmin bits per batch, dmax bits per batch]
__device__ float    g_tmpA[TOTAL];
__device__ float    g_tmpB[TOTAL];

// ---------------------------------------------------------------------------
// Point projection, matching XLA float32 op-for-op (no fmad contraction on the
// projection / quantization path; rintf == jnp.round half-to-even).
// ---------------------------------------------------------------------------
__device__ __forceinline__ void point_xform(
    const float* __restrict__ pp, const float* __restrict__ conf,
    const float* __restrict__ pose, const float* __restrict__ Kc,
    int b, int i, float& z, int& x, int& y, bool& valid)
{
    const float* ppb = pp + (size_t)b * 7 * NN;
    float p0 = ppb[0 * NN + i];
    float p1 = ppb[1 * NN + i];
    float p2 = ppb[2 * NN + i];
    float p3 = ppb[3 * NN + i];
    const float* P = pose + b * 16;
    float pc0 = P[0] * p0 + P[1] * p1 + P[2]  * p2 + P[3]  * p3;
    float pc1 = P[4] * p0 + P[5] * p1 + P[6]  * p2 + P[7]  * p3;
    float pc2 = P[8] * p0 + P[9] * p1 + P[10] * p2 + P[11] * p3;
    z = fabsf(pc2);
    const float* Kb = Kc + b * 9;
    float fx = Kb[0], cx = Kb[2], fy = Kb[4], cy = Kb[5];
    float xc = __fadd_rn(__fdiv_rn(__fmul_rn(pc0, fx), z), cx);
    float yc = __fadd_rn(__fdiv_rn(__fmul_rn(pc1, fy), z), cy);
    x = (int)rintf(xc);
    y = (int)rintf(yc);
    float cf = conf[(size_t)b * NN + i];
    valid = !(x < 0 || x >= WW || y < 0 || y >= HH ||
              z < ZNEAR || z > ZFAR || cf <= 0.0f);
}

// ---------------------------------------------------------------------------
__global__ void k_init()
{
    int t = blockIdx.x * blockDim.x + threadIdx.x;
    if (t < PLANE) g_key[t] = 0u;
    if (t < BB) {
        g_minmax[t]      = 0x7F800000u;  // +inf  (dmin init)
        g_minmax[BB + t] = 0u;           // +0    (dmax init; all values positive)
    }
}

// Per-batch min(inv_lo) / max(inv_hi). Positive floats compare identically as
// uint bit patterns, so atomicMin/Max on uints is exact float min/max.
__global__ void k_minmax(const float* __restrict__ pp, const float* __restrict__ conf,
                         const float* __restrict__ pose, const float* __restrict__ Kc)
{
    __shared__ float smn[BB][256];
    __shared__ float smx[BB][256];
    int tid = threadIdx.x;
    float mn[BB], mx[BB];
#pragma unroll
    for (int b = 0; b < BB; b++) { mn[b] = 3.0e38f; mx[b] = 0.0f; }

    int p = blockIdx.x * blockDim.x + tid;
    if (p < BB * NN) {
        int b = p / NN, i = p - b * NN;
        float z; int x, y; bool valid;
        point_xform(pp, conf, pose, Kc, b, i, z, x, y, valid);
        float lo = valid ? __fdiv_rn(1.0f, z) : 1.0e10f;
        float hi = valid ? lo : 1.0e-10f;
        mn[b] = lo; mx[b] = hi;
    }
#pragma unroll
    for (int b = 0; b < BB; b++) { smn[b][tid] = mn[b]; smx[b][tid] = mx[b]; }
    __syncthreads();
    for (int s = 128; s > 0; s >>= 1) {
        if (tid < s) {
#pragma unroll
            for (int b = 0; b < BB; b++) {
                smn[b][tid] = fminf(smn[b][tid], smn[b][tid + s]);
                smx[b][tid] = fmaxf(smx[b][tid], smx[b][tid + s]);
            }
        }
        __syncthreads();
    }
    if (tid == 0) {
#pragma unroll
        for (int b = 0; b < BB; b++) {
            atomicMin(&g_minmax[b],      __float_as_uint(smn[b][0]));
            atomicMax(&g_minmax[BB + b], __float_as_uint(smx[b][0]));
        }
    }
}

// Scatter: pack (do, point_idx) -> atomicMax per pixel.
// max do == min z across disjoint quantization bins (reference argmin);
// within a bin, max point_idx == last scatter update wins (XLA set order).
__global__ void k_scatter(const float* __restrict__ pp, const float* __restrict__ conf,
                          const float* __restrict__ pose, const float* __restrict__ Kc)
{
    int p = blockIdx.x * blockDim.x + threadIdx.x;
    if (p >= BB * NN) return;
    int b = p / NN, i = p - b * NN;
    float z; int x, y; bool valid;
    point_xform(pp, conf, pose, Kc, b, i, z, x, y, valid);
    if (!valid) return;
    float dmin = __uint_as_float(g_minmax[b]);
    float dmax = __uint_as_float(g_minmax[BB + b]);
    float inv  = __fdiv_rn(1.0f, z);
    float t = __fmul_rn(__fdiv_rn(__fsub_rn(inv, dmin), __fsub_rn(dmax, dmin)), 63.0f);
    int dq = (int)t;   // truncation == astype(int32) on nonneg
    unsigned key = ((((unsigned)dq) << 18) | (unsigned)i) + 1u;
    atomicMax(&g_key[b * HWp + y * WW + x], key);
}

// Resolve winners into flipped image planes (depth, conf, rgb).
__global__ void k_resolve(const float* __restrict__ pp, const float* __restrict__ conf,
                          const float* __restrict__ pose)
{
    int pix = blockIdx.x * blockDim.x + threadIdx.x;
    if (pix >= PLANE) return;
    int b  = pix / HWp;
    int rc = pix - b * HWp;
    int r  = rc / WW;
    int c  = rc - r * WW;
    int ysrc = HH - 1 - r;                       // vertical flip
    unsigned key = g_key[b * HWp + ysrc * WW + c];
    float d = 0.0f, cf = 0.0f, r0 = 0.0f, r1 = 0.0f, r2 = 0.0f;
    if (key) {
        int i = (int)((key - 1u) & 0x3FFFFu);
        const float* ppb = pp + (size_t)b * 7 * NN;
        float p0 = ppb[i], p1 = ppb[NN + i], p2 = ppb[2 * NN + i], p3 = ppb[3 * NN + i];
        const float* P = pose + b * 16;
        float pc2 = P[8] * p0 + P[9] * p1 + P[10] * p2 + P[11] * p3;
        d  = fabsf(pc2);
        cf = fmaxf(conf[(size_t)b * NN + i], 0.0f);
        r0 = ppb[4 * NN + i];
        r1 = ppb[5 * NN + i];
        r2 = ppb[6 * NN + i];
    }
    g_tmpA[pix]         = d;
    g_tmpA[PLANE + pix] = cf;
    int rgbbase = 2 * PLANE + (b * 3) * HWp + r * WW + c;
    g_tmpA[rgbbase]           = r0;
    g_tmpA[rgbbase + HWp]     = r1;
    g_tmpA[rgbbase + 2 * HWp] = r2;
}

// One hole-filling iteration. Conv pads with 0; maxpool pads with -inf
// (i.e. max over in-bounds taps only).
__global__ void k_fill(const float* __restrict__ src, float* __restrict__ dst,
                       const float* __restrict__ flt)
{
    int pix = blockIdx.x * blockDim.x + threadIdx.x;
    if (pix >= PLANE) return;
    int b  = pix / HWp;
    int rc = pix - b * HWp;
    int r  = rc / WW;
    int c  = rc - r * WW;

    const float* dep = src + b * HWp;
    float d9[9];
    float s = 0.0f;
#pragma unroll
    for (int dy = -1; dy <= 1; dy++)
#pragma unroll
        for (int dx = -1; dx <= 1; dx++) {
            int rr = r + dy, cc = c + dx;
            float v = (rr >= 0 && rr < HH && cc >= 0 && cc < WW) ? dep[rr * WW + cc] : 0.0f;
            d9[(dy + 1) * 3 + (dx + 1)] = v;
            s += v;
        }
    float center = d9[4];
    bool fill = false;
    if (s > 0.0f && center <= 0.0f) {
        float prod = 1.0f;
#pragma unroll
        for (int f = 0; f < 8; f++) {
            float o = 0.0f;
#pragma unroll
            for (int k = 0; k < 9; k++) o += d9[k] * flt[f * 9 + k];
            prod *= o;
        }
        fill = fabsf(prod) > 1e-10f;
    }

    int off[5];
    off[0] = b * HWp;                        // depth
    off[1] = PLANE + b * HWp;                // conf
    off[2] = 2 * PLANE + (b * 3 + 0) * HWp;  // rgb
    off[3] = 2 * PLANE + (b * 3 + 1) * HWp;
    off[4] = 2 * PLANE + (b * 3 + 2) * HWp;

    if (!fill) {
#pragma unroll
        for (int ch = 0; ch < 5; ch++)
            dst[off[ch] + r * WW + c] = src[off[ch] + r * WW + c];
    } else {
#pragma unroll
        for (int ch = 0; ch < 5; ch++) {
            const float* plane = src + off[ch];
            float mx = -3.4e38f;
            for (int dy = -1; dy <= 1; dy++)
                for (int dx = -1; dx <= 1; dx++) {
                    int rr = r + dy, cc = c + dx;
                    if (rr >= 0 && rr < HH && cc >= 0 && cc < WW)
                        mx = fmaxf(mx, plane[rr * WW + cc]);
                }
            dst[off[ch] + r * WW + c] = mx;
        }
    }
}

// ---------------------------------------------------------------------------
extern "C" void kernel_launch(void* const* d_in, const int* in_sizes, int n_in,
                              void* d_out, int out_size)
{
    const float* pp      = (const float*)d_in[0];  // [b,7,n]
    const float* conf    = (const float*)d_in[1];  // [b,n]
    const float* pose    = (const float*)d_in[2];  // [b,4,4]
    const float* Kc      = (const float*)d_in[3];  // [b,3,3]
    const float* filters = (const float*)d_in[4];  // [8,1,3,3]
    (void)in_sizes; (void)n_in; (void)out_size;

    float* tmpA = nullptr;
    float* tmpB = nullptr;
    cudaGetSymbolAddress((void**)&tmpA, g_tmpA);
    cudaGetSymbolAddress((void**)&tmpB, g_tmpB);

    const int T = 256;
    k_init<<<(PLANE + T - 1) / T, T>>>();
    k_minmax<<<(BB * NN + T - 1) / T, T>>>(pp, conf, pose, Kc);
    k_scatter<<<(BB * NN + T - 1) / T, T>>>(pp, conf, pose, Kc);
    k_resolve<<<(PLANE + T - 1) / T, T>>>(pp, conf, pose);
    k_fill<<<(PLANE + T - 1) / T, T>>>(tmpA, tmpB, filters);
    k_fill<<<(PLANE + T - 1) / T, T>>>(tmpB, (float*)d_out, filters);
}

// round 2
// speedup vs baseline: 1.0041x; 1.0041x over previous
#include <cuda_runtime.h>
#include <math.h>

// Problem-instance constants (setup_inputs: b=2, h=240, w=320, n=2*h*w)
#define BB 2
#define NN 153600
#define HH 240
#define WW 320
#define HWp (HH * WW)
#define PLANE (BB * HWp)        // 153600 pixels total
#define TOTAL (5 * PLANE)       // depth + conf + 3 rgb planes = 768000 floats
#define ZNEAR 0.1f
#define ZFAR 1000.0f

#define TX 32
#define TY 16

// Scratch (no allocations allowed -> __device__ globals)
__device__ __align__(16) unsigned g_key[PLANE];     // per-pixel packed winner key
__device__ unsigned g_minmax[2 * BB];               // dmin bits | dmax bits per batch
__device__ __align__(16) float    g_tmpA[TOTAL];    // composited planes (pre-fill)
__device__ float    g_pz[BB * NN];                  // cached per-point z
__device__ unsigned g_pxy[BB * NN];                 // cached pixel (y*W+x) or ~0 invalid

// ---------------------------------------------------------------------------
// init: zero key + planes, reset minmax. Vectorized.
// ---------------------------------------------------------------------------
__global__ void k_init()
{
    int t = blockIdx.x * blockDim.x + threadIdx.x;
    float4* a4 = (float4*)g_tmpA;
    uint4*  k4 = (uint4*)g_key;
    if (t < TOTAL / 4) a4[t] = make_float4(0.f, 0.f, 0.f, 0.f);
    if (t < PLANE / 4) k4[t] = make_uint4(0u, 0u, 0u, 0u);
    if (t < BB) {
        g_minmax[t]      = 0x7F800000u;  // +inf (dmin init)
        g_minmax[BB + t] = 0u;           // +0   (dmax init; values positive)
    }
}

// ---------------------------------------------------------------------------
// minmax + cache: full point transform once; store (z, pixel); reduce
// per-batch min(inv)/max(inv). Positive float bits compare as uints.
// Blocks never straddle batches (NN % 256 == 0).
// ---------------------------------------------------------------------------
__global__ void k_minmax(const float* __restrict__ pp, const float* __restrict__ conf,
                         const float* __restrict__ pose, const float* __restrict__ Kc)
{
    __shared__ float smn[256];
    __shared__ float smx[256];
    int tid = threadIdx.x;
    int p   = blockIdx.x * 256 + tid;
    int b   = blockIdx.x / (NN / 256);
    int i   = p - b * NN;

    const float* ppb = pp + (size_t)b * 7 * NN;
    float p0 = ppb[0 * NN + i];
    float p1 = ppb[1 * NN + i];
    float p2 = ppb[2 * NN + i];
    float p3 = ppb[3 * NN + i];
    const float* P = pose + b * 16;
    float pc0 = P[0] * p0 + P[1] * p1 + P[2]  * p2 + P[3]  * p3;
    float pc1 = P[4] * p0 + P[5] * p1 + P[6]  * p2 + P[7]  * p3;
    float pc2 = P[8] * p0 + P[9] * p1 + P[10] * p2 + P[11] * p3;
    float z = fabsf(pc2);
    const float* Kb = Kc + b * 9;
    float xc = __fadd_rn(__fdiv_rn(__fmul_rn(pc0, Kb[0]), z), Kb[2]);
    float yc = __fadd_rn(__fdiv_rn(__fmul_rn(pc1, Kb[4]), z), Kb[5]);
    int x = (int)rintf(xc);
    int y = (int)rintf(yc);
    float cf = conf[(size_t)b * NN + i];
    bool valid = !(x < 0 || x >= WW || y < 0 || y >= HH ||
                   z < ZNEAR || z > ZFAR || cf <= 0.0f);

    float inv = __fdiv_rn(1.0f, z);
    g_pz[p]  = z;
    g_pxy[p] = valid ? (unsigned)(y * WW + x) : 0xFFFFFFFFu;

    smn[tid] = valid ? inv : 1.0e10f;
    smx[tid] = valid ? inv : 1.0e-10f;
    __syncthreads();
    for (int s = 128; s > 0; s >>= 1) {
        if (tid < s) {
            smn[tid] = fminf(smn[tid], smn[tid + s]);
            smx[tid] = fmaxf(smx[tid], smx[tid + s]);
        }
        __syncthreads();
    }
    if (tid == 0) {
        atomicMin(&g_minmax[b],      __float_as_uint(smn[0]));
        atomicMax(&g_minmax[BB + b], __float_as_uint(smx[0]));
    }
}

// ---------------------------------------------------------------------------
// scatter: pack (do, point_idx)+1 -> atomicMax per pixel.
// max do == min z across disjoint bins; within a bin, max idx == last-wins.
// ---------------------------------------------------------------------------
__global__ void k_scatter()
{
    int p = blockIdx.x * blockDim.x + threadIdx.x;
    if (p >= BB * NN) return;
    unsigned pxy = g_pxy[p];
    if (pxy == 0xFFFFFFFFu) return;
    int b = p / NN, i = p - b * NN;
    float dmin = __uint_as_float(g_minmax[b]);
    float dmax = __uint_as_float(g_minmax[BB + b]);
    float inv  = __fdiv_rn(1.0f, g_pz[p]);
    float t = __fmul_rn(__fdiv_rn(__fsub_rn(inv, dmin), __fsub_rn(dmax, dmin)), 63.0f);
    int dq = (int)t;
    unsigned key = ((((unsigned)dq) << 18) | (unsigned)i) + 1u;
    atomicMax(&g_key[b * HWp + pxy], key);
}

// ---------------------------------------------------------------------------
// resolve (point-driven): winner writes its payload to flipped planes.
// Reads are coalesced point-indexed; key read hits L2.
// ---------------------------------------------------------------------------
__global__ void k_resolve(const float* __restrict__ pp, const float* __restrict__ conf)
{
    int p = blockIdx.x * blockDim.x + threadIdx.x;
    if (p >= BB * NN) return;
    unsigned pxy = g_pxy[p];
    if (pxy == 0xFFFFFFFFu) return;
    int b = p / NN, i = p - b * NN;
    unsigned key = g_key[b * HWp + pxy];
    if (((key - 1u) & 0x3FFFFu) != (unsigned)i) return;

    float z  = g_pz[p];
    float cf = fmaxf(conf[(size_t)b * NN + i], 0.0f);
    const float* ppb = pp + (size_t)b * 7 * NN;
    float r0 = ppb[4 * NN + i];
    float r1 = ppb[5 * NN + i];
    float r2 = ppb[6 * NN + i];

    int y = (int)(pxy / WW), x = (int)(pxy - (unsigned)y * WW);
    int rf = HH - 1 - y;                       // vertical flip
    int base = b * HWp + rf * WW + x;
    g_tmpA[base]         = z;
    g_tmpA[PLANE + base] = cf;
    int rgbbase = 2 * PLANE + (b * 3) * HWp + rf * WW + x;
    g_tmpA[rgbbase]           = r0;
    g_tmpA[rgbbase + HWp]     = r1;
    g_tmpA[rgbbase + 2 * HWp] = r2;
}

// ---------------------------------------------------------------------------
// Fused double hole-fill. Tile TXxTY; iter1 computed on tile+1 halo from a
// tile+2-halo smem stage; iter2 on the tile from iter1 smem. Conv pads 0,
// maxpool pads -inf (skip OOB via global coords).
// ---------------------------------------------------------------------------
__global__ void k_fill2(const float* __restrict__ src, float* __restrict__ dst,
                        const float* __restrict__ flt_g)
{
    __shared__ float s0[5][TY + 4][TX + 4];
    __shared__ float s1[5][TY + 2][TX + 2];
    __shared__ float flt[72];

    int b  = blockIdx.z;
    int ox = blockIdx.x * TX, oy = blockIdx.y * TY;
    int tid = threadIdx.y * TX + threadIdx.x;   // 0..511

    if (tid < 72) flt[tid] = flt_g[tid];

    int off[5];
    off[0] = b * HWp;
    off[1] = PLANE + b * HWp;
    off[2] = 2 * PLANE + (b * 3 + 0) * HWp;
    off[3] = 2 * PLANE + (b * 3 + 1) * HWp;
    off[4] = 2 * PLANE + (b * 3 + 2) * HWp;

    // stage 0: load tile + halo2, OOB -> 0
    const int L0 = (TY + 4) * (TX + 4);
    for (int idx = tid; idx < 5 * L0; idx += TX * TY) {
        int ch  = idx / L0;
        int rem = idx - ch * L0;
        int ly  = rem / (TX + 4), lx = rem - ly * (TX + 4);
        int gy  = oy + ly - 2, gx = ox + lx - 2;
        float v = (gy >= 0 && gy < HH && gx >= 0 && gx < WW)
                  ? src[off[ch] + gy * WW + gx] : 0.0f;
        s0[ch][ly][lx] = v;
    }
    __syncthreads();

    // stage 1: iteration 1 on tile + halo1 -> s1. Outside-image positions -> 0.
    const int L1 = (TY + 2) * (TX + 2);
    for (int idx = tid; idx < L1; idx += TX * TY) {
        int ly = idx / (TX + 2), lx = idx - ly * (TX + 2);
        int gy = oy + ly - 1, gx = ox + lx - 1;
        if (gy < 0 || gy >= HH || gx < 0 || gx >= WW) {
#pragma unroll
            for (int ch = 0; ch < 5; ch++) s1[ch][ly][lx] = 0.0f;
            continue;
        }
        float d9[9]; float s = 0.0f;
#pragma unroll
        for (int dy = -1; dy <= 1; dy++)
#pragma unroll
            for (int dx = -1; dx <= 1; dx++) {
                float v = s0[0][ly + 1 + dy][lx + 1 + dx];   // OOB stored 0
                d9[(dy + 1) * 3 + (dx + 1)] = v;
                s += v;
            }
        float center = d9[4];
        bool fill = false;
        if (s > 0.0f && center <= 0.0f) {
            float prod = 1.0f;
#pragma unroll
            for (int f = 0; f < 8; f++) {
                float o = 0.0f;
#pragma unroll
                for (int k = 0; k < 9; k++) o += d9[k] * flt[f * 9 + k];
                prod *= o;
            }
            fill = fabsf(prod) > 1e-10f;
        }
        if (!fill) {
#pragma unroll
            for (int ch = 0; ch < 5; ch++) s1[ch][ly][lx] = s0[ch][ly + 1][lx + 1];
        } else {
#pragma unroll
            for (int ch = 0; ch < 5; ch++) {
                float mx = -3.4e38f;
#pragma unroll
                for (int dy = -1; dy <= 1; dy++)
#pragma unroll
                    for (int dx = -1; dx <= 1; dx++) {
                        int rr = gy + dy, cc = gx + dx;
                        if (rr >= 0 && rr < HH && cc >= 0 && cc < WW)
                            mx = fmaxf(mx, s0[ch][ly + 1 + dy][lx + 1 + dx]);
                    }
                s1[ch][ly][lx] = mx;
            }
        }
    }
    __syncthreads();

    // stage 2: iteration 2 on the tile -> dst
    {
        int ty = threadIdx.y, tx = threadIdx.x;
        int gy = oy + ty, gx = ox + tx;     // dims divide evenly
        float d9[9]; float s = 0.0f;
#pragma unroll
        for (int dy = -1; dy <= 1; dy++)
#pragma unroll
            for (int dx = -1; dx <= 1; dx++) {
                float v = s1[0][ty + 1 + dy][tx + 1 + dx];   // outside-image = 0
                d9[(dy + 1) * 3 + (dx + 1)] = v;
                s += v;
            }
        float center = d9[4];
        bool fill = false;
        if (s > 0.0f && center <= 0.0f) {
            float prod = 1.0f;
#pragma unroll
            for (int f = 0; f < 8; f++) {
                float o = 0.0f;
#pragma unroll
                for (int k = 0; k < 9; k++) o += d9[k] * flt[f * 9 + k];
                prod *= o;
            }
            fill = fabsf(prod) > 1e-10f;
        }
        if (!fill) {
#pragma unroll
            for (int ch = 0; ch < 5; ch++)
                dst[off[ch] + gy * WW + gx] = s1[ch][ty + 1][tx + 1];
        } else {
#pragma unroll
            for (int ch = 0; ch < 5; ch++) {
                float mx = -3.4e38f;
#pragma unroll
                for (int dy = -1; dy <= 1; dy++)
#pragma unroll
                    for (int dx = -1; dx <= 1; dx++) {
                        int rr = gy + dy, cc = gx + dx;
                        if (rr >= 0 && rr < HH && cc >= 0 && cc < WW)
                            mx = fmaxf(mx, s1[ch][ty + 1 + dy][tx + 1 + dx]);
                    }
                dst[off[ch] + gy * WW + gx] = mx;
            }
        }
    }
}

// ---------------------------------------------------------------------------
extern "C" void kernel_launch(void* const* d_in, const int* in_sizes, int n_in,
                              void* d_out, int out_size)
{
    const float* pp      = (const float*)d_in[0];  // [b,7,n]
    const float* conf    = (const float*)d_in[1];  // [b,n]
    const float* pose    = (const float*)d_in[2];  // [b,4,4]
    const float* Kc      = (const float*)d_in[3];  // [b,3,3]
    const float* filters = (const float*)d_in[4];  // [8,1,3,3]
    (void)in_sizes; (void)n_in; (void)out_size;

    float* tmpA = nullptr;
    cudaGetSymbolAddress((void**)&tmpA, g_tmpA);

    const int T = 256;
    k_init   <<<(TOTAL / 4 + T - 1) / T, T>>>();
    k_minmax <<<BB * NN / T, T>>>(pp, conf, pose, Kc);
    k_scatter<<<(BB * NN + T - 1) / T, T>>>();
    k_resolve<<<(BB * NN + T - 1) / T, T>>>(pp, conf);
    dim3 fg(WW / TX, HH / TY, BB);
    dim3 fb(TX, TY);
    k_fill2<<<fg, fb>>>(tmpA, (float*)d_out, filters);
}